// round 13
// baseline (speedup 1.0000x reference)
#include <cuda_runtime.h>
#include <cstdint>

#define N_NODES 100000
#define N_EDGES 1600000
#define IN_F    128
#define OUT_F   32

typedef unsigned long long u64;

// Scratch (__device__ globals; no allocation anywhere in this file).
__device__ int   g_deg[N_NODES];              // indeg (memset 0 each call)
__device__ float g_dis[N_NODES];              // rsqrt(indeg+1)
__device__ u64   g_W2 [(IN_F / 2) * OUT_F];   // packed W pairs [k2][f]
__device__ float g_h  [N_NODES * OUT_F];      // RAW h = x @ W^T
__device__ __align__(16) int g_ptr [N_NODES + 4];
__device__ __align__(16) int g_fill[N_NODES + 4];
__device__ u64   g_csr2[N_EDGES];             // (f32bits(dis[src])<<32) | src
#define SCAN_NB 98                            // ceil(100000/1024)
__device__ u64   g_stat[SCAN_NB];             // lookback: (sum<<2)|flag (0/1=agg/2=prefix)

#define DEG_BLK (N_EDGES / 256)               // 6250
#define LIN_BLK ((N_NODES + 63) / 64)         // 1563

// ---------------------------------------------------------------------------
// L1: grid-fused pre-pass: deg count | W pack | scan-status zero.
__global__ void k_pre(const int* __restrict__ ei, const float* __restrict__ W) {
    int bid = blockIdx.x, t = threadIdx.x;
    if (bid < DEG_BLK) {
        int e = bid * 256 + t;                       // exact: 6250*256 = 1.6M
        atomicAdd(&g_deg[ei[N_EDGES + e]], 1);
    } else {
        int b2 = bid - DEG_BLK;
        if (b2 < 8) {                                // W pack: 2048 elems
            int i  = b2 * 256 + t;
            int k2 = i >> 5, f = i & 31;
            float w0 = W[f * IN_F + 2 * k2];
            float w1 = W[f * IN_F + 2 * k2 + 1];
            g_W2[i] = ((u64)__float_as_uint(w1) << 32) | (u64)__float_as_uint(w0);
        } else {
            if (t < SCAN_NB) g_stat[t] = 0;          // reset lookback state
        }
    }
}

// ---------------------------------------------------------------------------
// L2: single-pass exclusive scan of indeg (decoupled lookback) -> ptr, fill, dis.
__device__ __forceinline__ void stat_pub(int bid, int val, unsigned flag) {
    atomicExch(&g_stat[bid], ((u64)(unsigned)val << 2) | (u64)flag);
}

__global__ __launch_bounds__(256) void k_scan() {
    __shared__ int ws[8], wexcl_s[8];
    __shared__ int s_btot, s_prefix;
    int t = threadIdx.x, lane = t & 31, wid = t >> 5, bid = blockIdx.x;
    int i0 = bid * 1024 + t * 4;

    int va[4];
    #pragma unroll
    for (int j = 0; j < 4; j++)
        va[j] = (i0 + j < N_NODES) ? g_deg[i0 + j] : 0;   // indeg
    int s01 = va[0] + va[1], s012 = s01 + va[2], tsum = s012 + va[3];

    int inc = tsum;                                   // warp inclusive scan
    #pragma unroll
    for (int o = 1; o < 32; o <<= 1) {
        int n = __shfl_up_sync(0xffffffffu, inc, o);
        if (lane >= o) inc += n;
    }
    if (lane == 31) ws[wid] = inc;
    __syncthreads();
    if (wid == 0) {
        int wv = (lane < 8) ? ws[lane] : 0;
        int wi = wv;
        #pragma unroll
        for (int o = 1; o < 8; o <<= 1) {
            int n = __shfl_up_sync(0xffffffffu, wi, o);
            if (lane >= o) wi += n;
        }
        if (lane < 8) wexcl_s[lane] = wi - wv;
        if (lane == 7) s_btot = wi;                   // block total
    }
    __syncthreads();

    if (t == 0) {                                     // decoupled lookback
        int btot = s_btot, prefix = 0;
        if (bid == 0) {
            stat_pub(0, btot, 2u);
        } else {
            stat_pub(bid, btot, 1u);
            int i = bid - 1;
            while (true) {
                u64 s;
                do { s = *((volatile u64*)&g_stat[i]); } while ((s & 3ull) == 0ull);
                prefix += (int)(unsigned)(s >> 2);
                if ((s & 3ull) == 2ull) break;
                i--;
            }
            stat_pub(bid, prefix + btot, 2u);
        }
        s_prefix = prefix;
    }
    __syncthreads();

    int texcl = s_prefix + wexcl_s[wid] + (inc - tsum);
    int4 p = make_int4(texcl, texcl + va[0], texcl + s01, texcl + s012);
    if (i0 + 3 < N_NODES) {
        *(int4*)&g_ptr [i0] = p;
        *(int4*)&g_fill[i0] = p;
    } else {
        int pv[4] = {p.x, p.y, p.z, p.w};
        for (int j = 0; j < 4 && i0 + j < N_NODES; j++) {
            g_ptr[i0 + j] = pv[j]; g_fill[i0 + j] = pv[j];
        }
    }
    #pragma unroll
    for (int j = 0; j < 4; j++)
        if (i0 + j < N_NODES) g_dis[i0 + j] = rsqrtf((float)(va[j] + 1));
    if (bid == 0 && t == 0) g_ptr[N_NODES] = N_EDGES;
}

// ---------------------------------------------------------------------------
// L3: grid-fused main pass: linear (raw h, blocks [0,LIN_BLK)) concurrent with
// CSR build (blocks [LIN_BLK, LIN_BLK+DEG_BLK)). CSR entries carry dis[src].
#define FFMA2(acc, a, b) \
    asm("fma.rn.f32x2 %0, %1, %2, %0;" : "+l"(acc) : "l"(a), "l"(b))
#define CP_ASYNC16(saddr, gptr) \
    asm volatile("cp.async.cg.shared.global [%0], [%1], 16;" \
                 :: "r"(saddr), "l"(gptr) : "memory")

__global__ __launch_bounds__(256) void k_main(const float* __restrict__ x,
                                              const int* __restrict__ ei) {
    __shared__ u64   sW2[IN_F / 2][OUT_F];
    __shared__ float sx[64][IN_F];
    int tid = threadIdx.x;

    if (blockIdx.x >= LIN_BLK) {                      // --- CSR role ---
        int e = (blockIdx.x - LIN_BLK) * 256 + tid;   // exact 1.6M
        int dst = ei[N_EDGES + e];
        int src = ei[e];
        int pos = atomicAdd(&g_fill[dst], 1);
        g_csr2[pos] = ((u64)__float_as_uint(g_dis[src]) << 32) | (u64)(unsigned)src;
        return;
    }

    // --- linear role: h = x @ W^T (raw), FFMA2 with shared-staged operands ---
    int node0 = blockIdx.x * 64;
    bool full = (node0 + 64 <= N_NODES);

    const float4* xg = (const float4*)(x + (size_t)node0 * IN_F);
    float4* sx4 = (float4*)sx;
    if (full) {
        unsigned sbase;
        asm("{ .reg .u64 t; cvta.to.shared.u64 t, %1; cvt.u32.u64 %0, t; }"
            : "=r"(sbase) : "l"(sx4));
        #pragma unroll
        for (int i = 0; i < 8; i++) {
            int idx = tid + i * 256;
            CP_ASYNC16(sbase + idx * 16, xg + idx);
        }
        asm volatile("cp.async.commit_group;" ::: "memory");
    } else {
        #pragma unroll
        for (int i = 0; i < 8; i++) {
            int idx = tid + i * 256;
            sx4[idx] = (node0 + (idx >> 5) < N_NODES) ? xg[idx]
                                                      : make_float4(0.f, 0.f, 0.f, 0.f);
        }
    }
    {
        u64* sW = &sW2[0][0];
        #pragma unroll
        for (int i = 0; i < 8; i++)
            sW[tid + i * 256] = g_W2[tid + i * 256];
    }
    if (full) asm volatile("cp.async.wait_group 0;" ::: "memory");
    __syncthreads();

    int warp = tid >> 5;
    int f    = tid & 31;
    int nb   = warp * 8;

    u64 acc2[8];
    #pragma unroll
    for (int n = 0; n < 8; n++) acc2[n] = 0ull;

    #pragma unroll 8
    for (int k4 = 0; k4 < IN_F / 4; k4++) {
        u64 wa = sW2[2 * k4 + 0][f];
        u64 wb = sW2[2 * k4 + 1][f];
        #pragma unroll
        for (int n = 0; n < 8; n++) {
            ulonglong2 xv = *(const ulonglong2*)&sx[nb + n][k4 * 4];
            FFMA2(acc2[n], xv.x, wa);
            FFMA2(acc2[n], xv.y, wb);
        }
    }

    #pragma unroll
    for (int n = 0; n < 8; n++) {
        int node = node0 + nb + n;
        if (node < N_NODES) {
            float lo = __uint_as_float((unsigned)(acc2[n] & 0xFFFFFFFFull));
            float hi = __uint_as_float((unsigned)(acc2[n] >> 32));
            g_h[node * OUT_F + f] = lo + hi;          // RAW h (no dis dependency)
        }
    }
}

// ---------------------------------------------------------------------------
// L4: aggregate + finalize. Warp per node, lane = feature.
// acc = h_i*dis_i + sum_j dis_j * h_j ; out = acc*dis_i + b.
__global__ __launch_bounds__(256) void k_agg(const float* __restrict__ b,
                                             float* __restrict__ out) {
    int gtid = blockIdx.x * blockDim.x + threadIdx.x;
    int node = gtid >> 5;
    int lane = gtid & 31;

    float di  = g_dis[node];
    float acc = g_h[node * OUT_F + lane] * di;        // self-loop term
    int j   = g_ptr[node];
    int end = g_ptr[node + 1];

    for (; j + 4 <= end; j += 4) {
        u64 c0 = g_csr2[j];
        u64 c1 = g_csr2[j + 1];
        u64 c2 = g_csr2[j + 2];
        u64 c3 = g_csr2[j + 3];
        float v0 = g_h[(int)(unsigned)c0 * OUT_F + lane];   // 4 gathers in flight
        float v1 = g_h[(int)(unsigned)c1 * OUT_F + lane];
        float v2 = g_h[(int)(unsigned)c2 * OUT_F + lane];
        float v3 = g_h[(int)(unsigned)c3 * OUT_F + lane];
        acc = fmaf(__uint_as_float((unsigned)(c0 >> 32)), v0, acc);
        acc = fmaf(__uint_as_float((unsigned)(c1 >> 32)), v1, acc);
        acc = fmaf(__uint_as_float((unsigned)(c2 >> 32)), v2, acc);
        acc = fmaf(__uint_as_float((unsigned)(c3 >> 32)), v3, acc);
    }
    for (; j < end; j++) {
        u64 c = g_csr2[j];
        acc = fmaf(__uint_as_float((unsigned)(c >> 32)),
                   g_h[(int)(unsigned)c * OUT_F + lane], acc);
    }

    out[node * OUT_F + lane] = fmaf(acc, di, b[lane]);
}

// ---------------------------------------------------------------------------
extern "C" void kernel_launch(void* const* d_in, const int* in_sizes, int n_in,
                              void* d_out, int out_size) {
    const float* x  = (const float*)d_in[0];
    const int*   ei = (const int*)d_in[1];     // int32 (harness downcasts int64)
    const float* W  = (const float*)d_in[2];
    const float* b  = (const float*)d_in[3];
    float*       out = (float*)d_out;

    (void)in_sizes; (void)n_in; (void)out_size;

    void* pdeg = nullptr;
    cudaGetSymbolAddress(&pdeg, g_deg);                       // host query, capture-safe
    cudaMemsetAsync(pdeg, 0, N_NODES * sizeof(int), 0);       // memset node

    k_pre  <<<DEG_BLK + 9, 256>>>(ei, W);
    k_scan <<<SCAN_NB, 256>>>();
    k_main <<<LIN_BLK + DEG_BLK, 256>>>(x, ei);
    k_agg  <<<(N_NODES * 32) / 256, 256>>>(b, out);
}

// round 14
// speedup vs baseline: 1.7064x; 1.7064x over previous
#include <cuda_runtime.h>
#include <cuda_fp16.h>
#include <cstdint>

#define N_NODES 100000
#define N_EDGES 1600000
#define IN_F    128
#define OUT_F   32

typedef unsigned long long u64;

// Scratch (__device__ globals; no allocation anywhere in this file).
__device__ int    g_deg[N_NODES];
__device__ u64    g_W2 [(IN_F / 2) * OUT_F];   // packed W pairs: [k2][f]
__device__ __half g_hs [N_NODES * OUT_F];      // fp16 message: h * dis[node]
__device__ __align__(16) int g_ptr [N_NODES + 4];   // CSR row offsets
__device__ __align__(16) int g_fill[N_NODES + 4];   // fill cursors
__device__ int    g_part[128];                 // block partials for scan
__device__ int    g_csrc[N_EDGES];             // CSR: src ids bucketed by dst

// ---------------------------------------------------------------------------
// K1: deg=1 (self loop) + one-shot W pair packing.
__global__ void k_init(const float* __restrict__ W) {
    int i = blockIdx.x * blockDim.x + threadIdx.x;
    if (i < N_NODES) g_deg[i] = 1;
    if (i < (IN_F / 2) * OUT_F) {
        int k2 = i >> 5;
        int f  = i & 31;
        float w0 = W[f * IN_F + 2 * k2];
        float w1 = W[f * IN_F + 2 * k2 + 1];
        g_W2[i] = ((u64)__float_as_uint(w1) << 32) | (u64)__float_as_uint(w0);
    }
}

__global__ void k_deg_count(const int* __restrict__ ei) {
    int e = blockIdx.x * blockDim.x + threadIdx.x;
    if (e < N_EDGES) atomicAdd(&g_deg[ei[N_EDGES + e]], 1);
}

// ---------------------------------------------------------------------------
// Scan of indeg (= deg-1) over N_NODES. 1024 elems/block, 256 threads.
#define SCAN_NB ((N_NODES + 1023) / 1024)     // 98

__device__ __forceinline__ int4 load_indeg4(int i0) {
    int4 v;
    v.x = (i0 + 0 < N_NODES) ? g_deg[i0 + 0] - 1 : 0;
    v.y = (i0 + 1 < N_NODES) ? g_deg[i0 + 1] - 1 : 0;
    v.z = (i0 + 2 < N_NODES) ? g_deg[i0 + 2] - 1 : 0;
    v.w = (i0 + 3 < N_NODES) ? g_deg[i0 + 3] - 1 : 0;
    return v;
}

__global__ __launch_bounds__(256) void k_scan1() {       // block partial sums
    __shared__ int ws[8];
    int t = threadIdx.x, lane = t & 31, wid = t >> 5;
    int4 v = load_indeg4(blockIdx.x * 1024 + t * 4);
    int s = v.x + v.y + v.z + v.w;
    #pragma unroll
    for (int o = 16; o > 0; o >>= 1) s += __shfl_down_sync(0xffffffffu, s, o);
    if (lane == 0) ws[wid] = s;
    __syncthreads();
    if (t == 0) {
        int p = 0;
        #pragma unroll
        for (int w = 0; w < 8; w++) p += ws[w];
        g_part[blockIdx.x] = p;
    }
}

// Parallel exclusive scan of the 98 partials (warp-shuffle, 128 threads).
__global__ void k_scan2() {
    __shared__ int ws[4];
    int t = threadIdx.x, lane = t & 31, wid = t >> 5;
    int v = (t < SCAN_NB) ? g_part[t] : 0;
    int inc = v;
    #pragma unroll
    for (int o = 1; o < 32; o <<= 1) {
        int n = __shfl_up_sync(0xffffffffu, inc, o);
        if (lane >= o) inc += n;
    }
    if (lane == 31) ws[wid] = inc;
    __syncthreads();
    int wexcl = 0;
    #pragma unroll
    for (int w = 0; w < 4; w++) wexcl += (w < wid) ? ws[w] : 0;
    if (t < SCAN_NB) g_part[t] = wexcl + inc - v;        // exclusive
}

__global__ __launch_bounds__(256) void k_scan3() {       // full exclusive scan -> ptr, fill
    __shared__ int ws[8];
    __shared__ int wexcl_s[8];
    int t = threadIdx.x, lane = t & 31, wid = t >> 5;
    int i0 = blockIdx.x * 1024 + t * 4;
    int4 v = load_indeg4(i0);
    int s01  = v.x + v.y;
    int s012 = s01 + v.z;
    int tsum = s012 + v.w;

    int inc = tsum;
    #pragma unroll
    for (int o = 1; o < 32; o <<= 1) {
        int n = __shfl_up_sync(0xffffffffu, inc, o);
        if (lane >= o) inc += n;
    }
    if (lane == 31) ws[wid] = inc;
    __syncthreads();
    if (wid == 0) {
        int wv = (lane < 8) ? ws[lane] : 0;
        int wi = wv;
        #pragma unroll
        for (int o = 1; o < 8; o <<= 1) {
            int n = __shfl_up_sync(0xffffffffu, wi, o);
            if (lane >= o) wi += n;
        }
        if (lane < 8) wexcl_s[lane] = wi - wv;
    }
    __syncthreads();

    int texcl = g_part[blockIdx.x] + wexcl_s[wid] + (inc - tsum);
    int4 p = make_int4(texcl, texcl + v.x, texcl + s01, texcl + s012);
    if (i0 + 3 < N_NODES) {
        *(int4*)&g_ptr [i0] = p;
        *(int4*)&g_fill[i0] = p;
    } else {
        int pv[4] = {p.x, p.y, p.z, p.w};
        for (int j = 0; j < 4 && i0 + j < N_NODES; j++) {
            g_ptr[i0 + j] = pv[j]; g_fill[i0 + j] = pv[j];
        }
    }
    if (blockIdx.x == 0 && t == 0) g_ptr[N_NODES] = N_EDGES;
}

// ---------------------------------------------------------------------------
// CSR build: bucket src ids by dst.
__global__ void k_csr(const int* __restrict__ ei) {
    int e = blockIdx.x * blockDim.x + threadIdx.x;
    if (e < N_EDGES) {
        int dst = ei[N_EDGES + e];
        int pos = atomicAdd(&g_fill[dst], 1);
        g_csrc[pos] = ei[e];
    }
}

// ---------------------------------------------------------------------------
// K4: h = x @ W^T via packed f32x2 FMA, operands staged through shared.
// Message stored fp16 (halves gather payload downstream).
#define NODES_PER_WARP 8
#define NODES_PER_BLK  64
#define FFMA2(acc, a, b) \
    asm("fma.rn.f32x2 %0, %1, %2, %0;" : "+l"(acc) : "l"(a), "l"(b))
#define CP_ASYNC16(saddr, gptr) \
    asm volatile("cp.async.cg.shared.global [%0], [%1], 16;" \
                 :: "r"(saddr), "l"(gptr) : "memory")

__global__ __launch_bounds__(256) void k_linear(const float* __restrict__ x) {
    __shared__ u64   sW2[IN_F / 2][OUT_F];
    __shared__ float sx[NODES_PER_BLK][IN_F];

    int tid = threadIdx.x;
    int node0 = blockIdx.x * NODES_PER_BLK;
    bool full = (node0 + NODES_PER_BLK <= N_NODES);

    const float4* xg = (const float4*)(x + (size_t)node0 * IN_F);
    float4* sx4 = (float4*)sx;
    if (full) {
        unsigned sbase;
        asm("{ .reg .u64 t; cvta.to.shared.u64 t, %1; cvt.u32.u64 %0, t; }"
            : "=r"(sbase) : "l"(sx4));
        #pragma unroll
        for (int i = 0; i < 8; i++) {
            int idx = tid + i * 256;
            CP_ASYNC16(sbase + idx * 16, xg + idx);
        }
        asm volatile("cp.async.commit_group;" ::: "memory");
    } else {
        #pragma unroll
        for (int i = 0; i < 8; i++) {
            int idx = tid + i * 256;
            sx4[idx] = (node0 + (idx >> 5) < N_NODES) ? xg[idx]
                                                      : make_float4(0.f, 0.f, 0.f, 0.f);
        }
    }

    {
        u64* sW = &sW2[0][0];
        #pragma unroll
        for (int i = 0; i < 8; i++)
            sW[tid + i * 256] = g_W2[tid + i * 256];
    }

    if (full) asm volatile("cp.async.wait_group 0;" ::: "memory");
    __syncthreads();

    int warp = tid >> 5;
    int f    = tid & 31;
    int nb   = warp * NODES_PER_WARP;

    u64 acc2[NODES_PER_WARP];
    #pragma unroll
    for (int n = 0; n < NODES_PER_WARP; n++) acc2[n] = 0ull;

    #pragma unroll 8
    for (int k4 = 0; k4 < IN_F / 4; k4++) {
        u64 wa = sW2[2 * k4 + 0][f];
        u64 wb = sW2[2 * k4 + 1][f];
        #pragma unroll
        for (int n = 0; n < NODES_PER_WARP; n++) {
            ulonglong2 xv = *(const ulonglong2*)&sx[nb + n][k4 * 4];
            FFMA2(acc2[n], xv.x, wa);
            FFMA2(acc2[n], xv.y, wb);
        }
    }

    #pragma unroll
    for (int n = 0; n < NODES_PER_WARP; n++) {
        int node = node0 + nb + n;
        if (node < N_NODES) {
            float lo = __uint_as_float((unsigned)(acc2[n] & 0xFFFFFFFFull));
            float hi = __uint_as_float((unsigned)(acc2[n] >> 32));
            float d  = rsqrtf((float)g_deg[node]);
            g_hs[node * OUT_F + f] = __float2half((lo + hi) * d);
        }
    }
}

// ---------------------------------------------------------------------------
// K5: aggregate + finalize. Warp per node, lane = feature. fp16 gathers
// (64B/row = 2 sectors), fp32 accumulation, MLP=4.
__global__ __launch_bounds__(256) void k_aggregate(const float* __restrict__ b,
                                                   float* __restrict__ out) {
    int gtid = blockIdx.x * blockDim.x + threadIdx.x;
    int node = gtid >> 5;
    int lane = gtid & 31;

    float acc = __half2float(g_hs[node * OUT_F + lane]);   // self-loop term
    int j   = g_ptr[node];
    int end = g_ptr[node + 1];

    for (; j + 4 <= end; j += 4) {
        int s0 = g_csrc[j];                           // warp-broadcast index loads
        int s1 = g_csrc[j + 1];
        int s2 = g_csrc[j + 2];
        int s3 = g_csrc[j + 3];
        __half v0 = g_hs[s0 * OUT_F + lane];          // 4 gathers in flight
        __half v1 = g_hs[s1 * OUT_F + lane];
        __half v2 = g_hs[s2 * OUT_F + lane];
        __half v3 = g_hs[s3 * OUT_F + lane];
        acc += __half2float(v0);
        acc += __half2float(v1);
        acc += __half2float(v2);
        acc += __half2float(v3);
    }
    for (; j < end; j++)
        acc += __half2float(g_hs[g_csrc[j] * OUT_F + lane]);

    float d = rsqrtf((float)g_deg[node]);
    out[node * OUT_F + lane] = fmaf(acc, d, b[lane]);
}

// ---------------------------------------------------------------------------
extern "C" void kernel_launch(void* const* d_in, const int* in_sizes, int n_in,
                              void* d_out, int out_size) {
    const float* x  = (const float*)d_in[0];
    const int*   ei = (const int*)d_in[1];     // int32 (harness downcasts int64)
    const float* W  = (const float*)d_in[2];
    const float* b  = (const float*)d_in[3];
    float*       out = (float*)d_out;

    (void)in_sizes; (void)n_in; (void)out_size;

    k_init     <<<(N_NODES + 255) / 256, 256>>>(W);
    k_deg_count<<<(N_EDGES + 255) / 256, 256>>>(ei);
    k_scan1    <<<SCAN_NB, 256>>>();
    k_scan2    <<<1, 128>>>();
    k_scan3    <<<SCAN_NB, 256>>>();
    k_csr      <<<(N_EDGES + 255) / 256, 256>>>(ei);
    k_linear   <<<(N_NODES + NODES_PER_BLK - 1) / NODES_PER_BLK, 256>>>(x);
    k_aggregate<<<(N_NODES * 32) / 256, 256>>>(b, out);
}

// round 15
// speedup vs baseline: 1.8874x; 1.1060x over previous
#include <cuda_runtime.h>
#include <cuda_fp16.h>
#include <cstdint>

#define N_NODES 100000
#define N_EDGES 1600000
#define IN_F    128
#define OUT_F   32

typedef unsigned long long u64;

// Scratch (__device__ globals; no allocation anywhere in this file).
__device__ int    g_deg[N_NODES];              // indeg (memset to 0 each call)
__device__ u64    g_W2 [(IN_F / 2) * OUT_F];   // packed W pairs: [k2][f]
__device__ __half g_hs [N_NODES * OUT_F];      // fp16 message: h * dis[node]
__device__ __align__(16) int g_ptr [N_NODES + 4];   // CSR row offsets
__device__ __align__(16) int g_fill[N_NODES + 4];   // fill cursors
__device__ int    g_csrc[N_EDGES];             // CSR: src ids bucketed by dst

#define SCAN_NB ((N_NODES + 1023) / 1024)      // 98
__device__ u64    g_stat[SCAN_NB];             // lookback state: (sum<<2)|flag

#define DEG_BLK (N_EDGES / 256)                // 6250 (exact)
#define LIN_BLK ((N_NODES + 63) / 64)          // 1563

// ---------------------------------------------------------------------------
// L1: grid-fused pre-pass: indeg count | W pack | lookback-state zero.
__global__ void k_pre(const int* __restrict__ ei, const float* __restrict__ W) {
    int bid = blockIdx.x, t = threadIdx.x;
    if (bid < DEG_BLK) {
        int e = bid * 256 + t;                       // exact: 6250*256 = 1.6M
        atomicAdd(&g_deg[ei[N_EDGES + e]], 1);
    } else if (bid < DEG_BLK + 8) {                  // W pack: 2048 elems
        int i  = (bid - DEG_BLK) * 256 + t;
        int k2 = i >> 5, f = i & 31;
        float w0 = W[f * IN_F + 2 * k2];
        float w1 = W[f * IN_F + 2 * k2 + 1];
        g_W2[i] = ((u64)__float_as_uint(w1) << 32) | (u64)__float_as_uint(w0);
    } else {
        if (t < SCAN_NB) g_stat[t] = 0;              // reset lookback state
    }
}

// ---------------------------------------------------------------------------
// L2: single-pass exclusive scan of indeg (decoupled lookback) -> ptr, fill.
__device__ __forceinline__ void stat_pub(int bid, int val, unsigned flag) {
    atomicExch(&g_stat[bid], ((u64)(unsigned)val << 2) | (u64)flag);
}

__global__ __launch_bounds__(256) void k_scan() {
    __shared__ int ws[8], wexcl_s[8];
    __shared__ int s_btot, s_prefix;
    int t = threadIdx.x, lane = t & 31, wid = t >> 5, bid = blockIdx.x;
    int i0 = bid * 1024 + t * 4;

    int va[4];
    #pragma unroll
    for (int j = 0; j < 4; j++)
        va[j] = (i0 + j < N_NODES) ? g_deg[i0 + j] : 0;   // indeg
    int s01 = va[0] + va[1], s012 = s01 + va[2], tsum = s012 + va[3];

    int inc = tsum;                                   // warp inclusive scan
    #pragma unroll
    for (int o = 1; o < 32; o <<= 1) {
        int n = __shfl_up_sync(0xffffffffu, inc, o);
        if (lane >= o) inc += n;
    }
    if (lane == 31) ws[wid] = inc;
    __syncthreads();
    if (wid == 0) {
        int wv = (lane < 8) ? ws[lane] : 0;
        int wi = wv;
        #pragma unroll
        for (int o = 1; o < 8; o <<= 1) {
            int n = __shfl_up_sync(0xffffffffu, wi, o);
            if (lane >= o) wi += n;
        }
        if (lane < 8) wexcl_s[lane] = wi - wv;
        if (lane == 7) s_btot = wi;                   // block total
    }
    __syncthreads();

    if (t == 0) {                                     // decoupled lookback
        int btot = s_btot, prefix = 0;
        if (bid == 0) {
            stat_pub(0, btot, 2u);
        } else {
            stat_pub(bid, btot, 1u);
            int i = bid - 1;
            while (true) {
                u64 s;
                do { s = *((volatile u64*)&g_stat[i]); } while ((s & 3ull) == 0ull);
                prefix += (int)(unsigned)(s >> 2);
                if ((s & 3ull) == 2ull) break;
                i--;
            }
            stat_pub(bid, prefix + btot, 2u);
        }
        s_prefix = prefix;
    }
    __syncthreads();

    int texcl = s_prefix + wexcl_s[wid] + (inc - tsum);
    int4 p = make_int4(texcl, texcl + va[0], texcl + s01, texcl + s012);
    if (i0 + 3 < N_NODES) {
        *(int4*)&g_ptr [i0] = p;
        *(int4*)&g_fill[i0] = p;
    } else {
        int pv[4] = {p.x, p.y, p.z, p.w};
        for (int j = 0; j < 4 && i0 + j < N_NODES; j++) {
            g_ptr[i0 + j] = pv[j]; g_fill[i0 + j] = pv[j];
        }
    }
    if (bid == 0 && t == 0) g_ptr[N_NODES] = N_EDGES;
}

// ---------------------------------------------------------------------------
// L3: linear (FFMA2, shared-staged) + CSR-build tail phase in the SAME blocks.
// The ~9µs of scattered-atomic CSR work hides under the FMA wall.
#define NODES_PER_WARP 8
#define NODES_PER_BLK  64
#define FFMA2(acc, a, b) \
    asm("fma.rn.f32x2 %0, %1, %2, %0;" : "+l"(acc) : "l"(a), "l"(b))
#define CP_ASYNC16(saddr, gptr) \
    asm volatile("cp.async.cg.shared.global [%0], [%1], 16;" \
                 :: "r"(saddr), "l"(gptr) : "memory")

__global__ __launch_bounds__(256) void k_linear(const float* __restrict__ x,
                                                const int* __restrict__ ei) {
    __shared__ u64   sW2[IN_F / 2][OUT_F];
    __shared__ float sx[NODES_PER_BLK][IN_F];

    int tid = threadIdx.x;
    int node0 = blockIdx.x * NODES_PER_BLK;
    bool full = (node0 + NODES_PER_BLK <= N_NODES);

    const float4* xg = (const float4*)(x + (size_t)node0 * IN_F);
    float4* sx4 = (float4*)sx;
    if (full) {
        unsigned sbase;
        asm("{ .reg .u64 t; cvta.to.shared.u64 t, %1; cvt.u32.u64 %0, t; }"
            : "=r"(sbase) : "l"(sx4));
        #pragma unroll
        for (int i = 0; i < 8; i++) {
            int idx = tid + i * 256;
            CP_ASYNC16(sbase + idx * 16, xg + idx);
        }
        asm volatile("cp.async.commit_group;" ::: "memory");
    } else {
        #pragma unroll
        for (int i = 0; i < 8; i++) {
            int idx = tid + i * 256;
            sx4[idx] = (node0 + (idx >> 5) < N_NODES) ? xg[idx]
                                                      : make_float4(0.f, 0.f, 0.f, 0.f);
        }
    }

    {
        u64* sW = &sW2[0][0];
        #pragma unroll
        for (int i = 0; i < 8; i++)
            sW[tid + i * 256] = g_W2[tid + i * 256];
    }

    if (full) asm volatile("cp.async.wait_group 0;" ::: "memory");
    __syncthreads();

    int warp = tid >> 5;
    int f    = tid & 31;
    int nb   = warp * NODES_PER_WARP;

    u64 acc2[NODES_PER_WARP];
    #pragma unroll
    for (int n = 0; n < NODES_PER_WARP; n++) acc2[n] = 0ull;

    #pragma unroll 8
    for (int k4 = 0; k4 < IN_F / 4; k4++) {
        u64 wa = sW2[2 * k4 + 0][f];
        u64 wb = sW2[2 * k4 + 1][f];
        #pragma unroll
        for (int n = 0; n < NODES_PER_WARP; n++) {
            ulonglong2 xv = *(const ulonglong2*)&sx[nb + n][k4 * 4];
            FFMA2(acc2[n], xv.x, wa);
            FFMA2(acc2[n], xv.y, wb);
        }
    }

    #pragma unroll
    for (int n = 0; n < NODES_PER_WARP; n++) {
        int node = node0 + nb + n;
        if (node < N_NODES) {
            float lo = __uint_as_float((unsigned)(acc2[n] & 0xFFFFFFFFull));
            float hi = __uint_as_float((unsigned)(acc2[n] >> 32));
            float d  = rsqrtf((float)(g_deg[node] + 1));   // deg = indeg + 1
            g_hs[node * OUT_F + f] = __float2half((lo + hi) * d);
        }
    }

    // --- CSR tail: this block's 1024-edge chunk (independent of the above) ---
    #pragma unroll
    for (int i = 0; i < 4; i++) {
        int e = blockIdx.x * 1024 + i * 256 + tid;
        if (e < N_EDGES) {
            int dst = ei[N_EDGES + e];
            int pos = atomicAdd(&g_fill[dst], 1);
            g_csrc[pos] = ei[e];
        }
    }
}

// ---------------------------------------------------------------------------
// L4: aggregate + finalize. Warp per node, lane = feature. fp16 gathers,
// fp32 accumulation, MLP=4. Plain coalesced stores to d_out.
__global__ __launch_bounds__(256) void k_aggregate(const float* __restrict__ b,
                                                   float* __restrict__ out) {
    int gtid = blockIdx.x * blockDim.x + threadIdx.x;
    int node = gtid >> 5;
    int lane = gtid & 31;

    float acc = __half2float(g_hs[node * OUT_F + lane]);   // self-loop term
    int j   = g_ptr[node];
    int end = g_ptr[node + 1];

    for (; j + 4 <= end; j += 4) {
        int s0 = g_csrc[j];
        int s1 = g_csrc[j + 1];
        int s2 = g_csrc[j + 2];
        int s3 = g_csrc[j + 3];
        __half v0 = g_hs[s0 * OUT_F + lane];          // 4 gathers in flight
        __half v1 = g_hs[s1 * OUT_F + lane];
        __half v2 = g_hs[s2 * OUT_F + lane];
        __half v3 = g_hs[s3 * OUT_F + lane];
        acc += __half2float(v0);
        acc += __half2float(v1);
        acc += __half2float(v2);
        acc += __half2float(v3);
    }
    for (; j < end; j++)
        acc += __half2float(g_hs[g_csrc[j] * OUT_F + lane]);

    float d = rsqrtf((float)(g_deg[node] + 1));       // deg = indeg + 1
    out[node * OUT_F + lane] = fmaf(acc, d, b[lane]);
}

// ---------------------------------------------------------------------------
extern "C" void kernel_launch(void* const* d_in, const int* in_sizes, int n_in,
                              void* d_out, int out_size) {
    const float* x  = (const float*)d_in[0];
    const int*   ei = (const int*)d_in[1];     // int32 (harness downcasts int64)
    const float* W  = (const float*)d_in[2];
    const float* b  = (const float*)d_in[3];
    float*       out = (float*)d_out;

    (void)in_sizes; (void)n_in; (void)out_size;

    void* pdeg = nullptr;
    cudaGetSymbolAddress(&pdeg, g_deg);                    // capture-safe host query
    cudaMemsetAsync(pdeg, 0, N_NODES * sizeof(int), 0);    // memset node

    k_pre      <<<DEG_BLK + 9, 256>>>(ei, W);
    k_scan     <<<SCAN_NB, 256>>>();
    k_linear   <<<LIN_BLK, 256>>>(x, ei);
    k_aggregate<<<(N_NODES * 32) / 256, 256>>>(b, out);
}